// round 14
// baseline (speedup 1.0000x reference)
#include <cuda_runtime.h>
#include <cuda_bf16.h>
#include <cstdint>

#define B_   16
#define C_   192
#define TX_  512
#define TY_  2048
#define SEG_ 32
#define K2_  384          // 2*C
#define NEG_INF_ (-1e9f)
#define CH_  8            // DP chunk rows (skew/staging unit)
#define NLOAD_ 448        // dp loader lanes (14 warps)

// grid layout of fused kernel
#define GEMM0_   (B_)                 // 16
#define NGEMM_   (4 * 16 * 16)        // 1024 (128x128 tiles)
#define EPI0_    (GEMM0_ + NGEMM_)    // 1040
#define EPB_     64                   // epilogue CTAs per batch
#define NEPI_    (B_ * EPB_)          // 1024
#define ZSL0_    (EPI0_ + NEPI_)      // 2064
#define NCTAS_   (ZSL0_ + B_)         // 2080

// dp smem layout
#define DIRS_BYTES_   (TY_ * 64)                       // u8[2048][64] = 128KB
#define ROWBUF_BYTES_ (3 * CH_ * 128 * 16)             // 3 stages = 48KB
#define BND_OFF_      (DIRS_BYTES_ + ROWBUF_BYTES_)
#define FUSED_SMEM    (BND_OFF_ + (TY_ + 4) * 4)       // + bnd column

// ---------------- scratch (device globals: no runtime allocation) ----------------
__device__ float g_B[B_ * K2_ * TX_];
__device__ float g_cvec[B_ * TX_];
__device__ float g_negcent[(size_t)B_ * TY_ * TX_];  // 64 MB
__device__ int   g_idx[B_ * TY_];
__device__ int   g_cnt[B_ * 16];                     // per (b, 128-row band) completed n-tiles (target 4)
__device__ int   g_done[B_];                         // dp finished (g_idx valid) per batch

// ---------------- helpers ----------------
union F2 { float2 f; unsigned long long u; };

__device__ __forceinline__ unsigned long long ffma2(unsigned long long a,
                                                    unsigned long long b,
                                                    unsigned long long c) {
    unsigned long long d;
    asm("fma.rn.f32x2 %0, %1, %2, %3;" : "=l"(d) : "l"(a), "l"(b), "l"(c));
    return d;
}

__device__ __forceinline__ int ld_acq(const int* p) {
    int v;
    asm volatile("ld.acquire.gpu.global.b32 %0, [%1];" : "=r"(v) : "l"(p) : "memory");
    return v;
}
__device__ __forceinline__ void st_rel(int* p, int v) {
    asm volatile("st.release.gpu.global.b32 [%0], %1;" :: "l"(p), "r"(v) : "memory");
}

#define CP_ASYNC16(smem_u32, gptr) \
    asm volatile("cp.async.cg.shared.global [%0], [%1], 16;" :: "r"(smem_u32), "l"(gptr) : "memory")
#define CP_COMMIT() asm volatile("cp.async.commit_group;" ::: "memory")
#define CP_WAIT0()  asm volatile("cp.async.wait_group 0;" ::: "memory")

// ---------------- prep: B matrix + zero flags ----------------
__global__ void prep_kernel(const float* __restrict__ m_p, const float* __restrict__ logs_p) {
    int i = blockIdx.x * blockDim.x + threadIdx.x;   // over B*C*TX
    if (i >= B_ * C_ * TX_) return;
    if (i < B_ * 16) g_cnt[i] = 0;                   // reset producer flags every replay
    if (i < B_) g_done[i] = 0;
    int s = i % TX_;
    int c = (i / TX_) % C_;
    int b = i / (TX_ * C_);
    float lg = logs_p[i];
    float mp = m_p[i];
    float se = expf(-2.0f * lg);
    g_B[(b * K2_ + c) * TX_ + s]        = se;
    g_B[(b * K2_ + C_ + c) * TX_ + s]   = se * mp;
}

// ---------------- prep: per-column constant ----------------
__global__ void cvec_kernel(const float* __restrict__ m_p, const float* __restrict__ logs_p) {
    int b = blockIdx.x;
    int s = threadIdx.x;                              // 512 threads
    float acc = 0.f;
    for (int c = 0; c < C_; c++) {
        int off = (b * C_ + c) * TX_ + s;
        float lg = logs_p[off];
        float mp = m_p[off];
        float se = expf(-2.0f * lg);
        acc += -0.5f * se * mp * mp - lg;
    }
    g_cvec[b * TX_ + s] = acc;
}

// ---------------- fused: GEMM producers + DP consumers + gated epilogues ----------------
#define BM 128
#define BN 128
#define BK 16

__global__ void __launch_bounds__(512) fused_kernel(const float* __restrict__ z_p,
                                                    const float* __restrict__ m_p,
                                                    const float* __restrict__ logs_p,
                                                    const float* __restrict__ z,
                                                    const int* __restrict__ x_lengths,
                                                    const int* __restrict__ y_lengths,
                                                    const float* __restrict__ rand_u,
                                                    float* __restrict__ out_z,
                                                    float* __restrict__ out_ids,
                                                    float* __restrict__ out_attn,
                                                    float* __restrict__ out_m,
                                                    float* __restrict__ out_l)
{
    extern __shared__ char sdyn[];
    const int tid = threadIdx.x;
    const unsigned bid = blockIdx.x;

    if (bid < GEMM0_) {
        // ================= DP consumer CTA (batch b): 2 skewed compute warps + 14 loaders =================
        unsigned char* dirs8 = (unsigned char*)sdyn;                       // [TY_][64]
        float4* rowbuf = (float4*)(sdyn + DIRS_BYTES_);                    // [3][CH_][128]
        float*  bnd    = (float*)(sdyn + BND_OFF_);                        // [TY_+1]

        const int b    = bid;
        const int lane = tid & 31;
        const int w    = tid >> 5;                                         // 0..15
        const int t_x  = min(x_lengths[b], TX_);
        const int t_y  = min(y_lengths[b], TY_);
        const int nc   = (t_y + CH_ - 1) / CH_;                            // chunks of 8 rows

        const float4* src = (const float4*)(g_negcent + (size_t)b * TY_ * TX_);
        const uint32_t rb_u32 = (uint32_t)__cvta_generic_to_shared(rowbuf);
        const int* cntb = g_cnt + b * 16;

        if (tid == 0) bnd[0] = NEG_INF_;

        float v0 = NEG_INF_, v1 = NEG_INF_, v2 = NEG_INF_, v3 = NEG_INF_;
        float v4 = NEG_INF_, v5 = NEG_INF_, v6 = NEG_INF_, v7 = NEG_INF_;
        if (w == 0 && lane == 0) v0 = 0.0f;   // global col 0
        __syncthreads();

        // iterations: i loads chunk i; w0 computes chunk i-1; w1 computes chunk i-2
        for (int i = 0; i <= nc + 1; i++) {
            if (w >= 2) {
                if (i < nc) {
                    if ((i & 15) == 0) {                                   // new 128-row band
                        // EVERY loader warp must gate on the producer flag
                        if (lane == 0) while (ld_acq(&cntb[i >> 4]) < 4) { }
                        __syncwarp();
                    }
                    const int lid = tid - 64;                              // 0..447
                    const int t0 = i * CH_;
                    const uint32_t dstb = rb_u32 + (uint32_t)((i % 3) * CH_ * 128 * 16);
                    for (int p = lid; p < CH_ * 128; p += NLOAD_)
                        CP_ASYNC16(dstb + p * 16, src + (size_t)(t0 + (p >> 7)) * 128 + (p & 127));
                    CP_COMMIT();
                    CP_WAIT0();
                }
            } else {
                const int ch = i - 1 - w;                                  // w0: i-1; w1: i-2
                if (ch >= 0 && ch < nc) {
                    const float4* basep = rowbuf + (ch % 3) * CH_ * 128 + (w << 6) + (lane << 1);
                    const int t0 = ch * CH_;
                    float4 cA = basep[0], cB = basep[1];
#pragma unroll
                    for (int r = 0; r < CH_; r++) {
                        const int t = t0 + r;
                        float4 nA, nB;
                        if (r + 1 < CH_) { nA = basep[(r + 1) * 128]; nB = basep[(r + 1) * 128 + 1]; }

                        float lbv = bnd[t];                                 // broadcast LDS (used by w1 lane0)
                        float sh = __shfl_up_sync(0xffffffffu, v7, 1);
                        float left0 = (lane == 0) ? ((w == 1) ? lbv : NEG_INF_) : sh;

                        unsigned bits = 0u;
                        float d;
                        d = v7 - v6; bits |= (__float_as_uint(d) >> 24) & 0x80u; v7 = cB.w + fmaxf(v6, v7);
                        d = v6 - v5; bits |= (__float_as_uint(d) >> 25) & 0x40u; v6 = cB.z + fmaxf(v5, v6);
                        d = v5 - v4; bits |= (__float_as_uint(d) >> 26) & 0x20u; v5 = cB.y + fmaxf(v4, v5);
                        d = v4 - v3; bits |= (__float_as_uint(d) >> 27) & 0x10u; v4 = cB.x + fmaxf(v3, v4);
                        d = v3 - v2; bits |= (__float_as_uint(d) >> 28) & 0x08u; v3 = cA.w + fmaxf(v2, v3);
                        d = v2 - v1; bits |= (__float_as_uint(d) >> 29) & 0x04u; v2 = cA.z + fmaxf(v1, v2);
                        d = v1 - v0; bits |= (__float_as_uint(d) >> 30) & 0x02u; v1 = cA.y + fmaxf(v0, v1);
                        d = v0 - left0; bits |= (__float_as_uint(d) >> 31);      v0 = cA.x + fmaxf(left0, v0);

                        if (w == 0 && lane == 31) bnd[t + 1] = v7;
                        dirs8[t * 64 + (w << 5) + lane] = (unsigned char)bits;
                        cA = nA; cB = nB;
                    }
                }
            }
            __syncthreads();
        }

        // rows >= t_y: no path
        for (int t = t_y + tid; t < TY_; t += 512) g_idx[b * TY_ + t] = -1;
        __syncthreads();

        // backtrack (single lane), then publish
        if (tid == 0) {
            int idx = t_x - 1;
            for (int j = t_y - 1; j >= 0; j--) {
                g_idx[b * TY_ + j] = idx;
                unsigned word = dirs8[j * 64 + (idx >> 3)];
                idx -= (int)((word >> (idx & 7)) & 1u);
            }
            __threadfence();
            st_rel(&g_done[b], 1);
        }
        return;
    }

    if (bid < EPI0_) {
        // ================= GEMM producer CTA (512 threads, 128x128 tile) =================
        const int r    = bid - GEMM0_;
        const int nb   = r & 3;                   // 4 n-blocks
        const int b    = (r >> 2) & 15;           // 16 batches
        const int mblk = r >> 6;                  // 16 m-blocks of 128 rows (low bands first)
        const int m0   = mblk * BM;
        const int n0   = nb * BN;

        typedef float TileT[BK][BM];
        TileT* As = (TileT*)sdyn;                            // [2][16][128] 16KB
        TileT* Bs = (TileT*)(sdyn + 2 * BK * BM * 4);        // [2][16][128] 16KB

        const bool active = (m0 < y_lengths[b]) && (n0 < x_lengths[b]);

        if (active) {
            const int kRow  = tid >> 5;               // 0..15
            const int lcol  = (tid & 31) << 2;        // 0..124
            const int mBase = (tid >> 4) << 2;        // 0..124 (4 rows)
            const int nBase = (tid & 15) << 3;        // 0..120 (8 cols)

            const float* zpb = z_p + b * C_ * TY_;
            const float* Bb  = g_B + b * K2_ * TX_;

            F2 acc[4][4];
#pragma unroll
            for (int i = 0; i < 4; i++)
#pragma unroll
                for (int j = 0; j < 4; j++) { acc[i][j].f.x = 0.f; acc[i][j].f.y = 0.f; }

            float4 ra, rb;
            {
                int kk = kRow;
                int cA = (kk < C_) ? kk : kk - C_;
                ra = *(const float4*)(zpb + cA * TY_ + m0 + lcol);
                if (kk < C_) {
                    ra.x = -0.5f * ra.x * ra.x; ra.y = -0.5f * ra.y * ra.y;
                    ra.z = -0.5f * ra.z * ra.z; ra.w = -0.5f * ra.w * ra.w;
                }
                rb = *(const float4*)(Bb + kk * TX_ + n0 + lcol);
            }
            *(float4*)&As[0][kRow][lcol] = ra;
            *(float4*)&Bs[0][kRow][lcol] = rb;
            __syncthreads();

            const int NIT = K2_ / BK;   // 24
            for (int it = 0; it < NIT; ++it) {
                const int cur = it & 1;
                if (it + 1 < NIT) {
                    int kk = (it + 1) * BK + kRow;
                    int cA = (kk < C_) ? kk : kk - C_;
                    ra = *(const float4*)(zpb + cA * TY_ + m0 + lcol);
                    if (kk < C_) {
                        ra.x = -0.5f * ra.x * ra.x; ra.y = -0.5f * ra.y * ra.y;
                        ra.z = -0.5f * ra.z * ra.z; ra.w = -0.5f * ra.w * ra.w;
                    }
                    rb = *(const float4*)(Bb + kk * TX_ + n0 + lcol);
                }
#pragma unroll
                for (int k = 0; k < BK; k++) {
                    float4 a0 = *(const float4*)&As[cur][k][mBase];
                    float4 b0 = *(const float4*)&Bs[cur][k][nBase];
                    float4 b1 = *(const float4*)&Bs[cur][k][nBase + 4];
                    F2 bb[4];
                    bb[0].f = make_float2(b0.x, b0.y);
                    bb[1].f = make_float2(b0.z, b0.w);
                    bb[2].f = make_float2(b1.x, b1.y);
                    bb[3].f = make_float2(b1.z, b1.w);
                    float a[4] = {a0.x, a0.y, a0.z, a0.w};
#pragma unroll
                    for (int i = 0; i < 4; i++) {
                        F2 aa; aa.f = make_float2(a[i], a[i]);
#pragma unroll
                        for (int j = 0; j < 4; j++)
                            acc[i][j].u = ffma2(aa.u, bb[j].u, acc[i][j].u);
                    }
                }
                if (it + 1 < NIT) {
                    const int nxt = cur ^ 1;
                    *(float4*)&As[nxt][kRow][lcol] = ra;
                    *(float4*)&Bs[nxt][kRow][lcol] = rb;
                }
                __syncthreads();
            }

            // epilogue: add per-column constant and store
            float4 cv0 = *(const float4*)(g_cvec + b * TX_ + n0 + nBase);
            float4 cv1 = *(const float4*)(g_cvec + b * TX_ + n0 + nBase + 4);
            float* outbase = g_negcent + ((size_t)b * TY_ + m0 + mBase) * TX_ + n0 + nBase;
#pragma unroll
            for (int i = 0; i < 4; i++) {
                float4 o0, o1;
                o0.x = acc[i][0].f.x + cv0.x; o0.y = acc[i][0].f.y + cv0.y;
                o0.z = acc[i][1].f.x + cv0.z; o0.w = acc[i][1].f.y + cv0.w;
                o1.x = acc[i][2].f.x + cv1.x; o1.y = acc[i][2].f.y + cv1.y;
                o1.z = acc[i][3].f.x + cv1.z; o1.w = acc[i][3].f.y + cv1.w;
                float* op = outbase + (size_t)i * TX_;
                *(float4*)op       = o0;
                *(float4*)(op + 4) = o1;
            }
            __syncthreads();
        }

        // signal band completion (also for skipped tiles)
        if (tid == 0) {
            __threadfence();
            atomicAdd(&g_cnt[b * 16 + mblk], 1);
        }
        return;
    }

    if (bid < ZSL0_) {
        // ================= gated epilogue CTA: attn rows + m/logs gathers =================
        const int e    = bid - EPI0_;
        const int b    = e >> 6;                  // 64 CTAs per batch
        const int part = e & 63;

        __shared__ int s_ready;
        if (tid == 0) {
            while (ld_acq(&g_done[b]) == 0) { }
            s_ready = 1;
        }
        __syncthreads();
        (void)s_ready;

        // attn: rows [part*32, part*32+32)
        {
            const int base = b * TY_ + part * 32;
#pragma unroll
            for (int i = 0; i < 8; i++) {
                int p   = tid + i * 512;              // 0..4095
                int t   = base + (p >> 7);
                int c4  = p & 127;
                int idx = g_idx[t];
                int s0  = c4 * 4;
                float4 val = make_float4(0.f, 0.f, 0.f, 0.f);
                if (idx >= s0 && idx < s0 + 4) {
                    if (idx == s0)          val.x = 1.f;
                    else if (idx == s0 + 1) val.y = 1.f;
                    else if (idx == s0 + 2) val.z = 1.f;
                    else                    val.w = 1.f;
                }
                *(float4*)(out_attn + (size_t)t * TX_ + s0) = val;
            }
        }

        // gather: elements [part*6144, +6144) of batch b's 192*2048
        {
            const int ebase = part * 6144;
#pragma unroll
            for (int i = 0; i < 12; i++) {
                int p = ebase + tid + i * 512;
                int t = p & (TY_ - 1);
                int c = p >> 11;
                int idx = g_idx[b * TY_ + t];
                float vm = 0.f, vl = 0.f;
                if (idx >= 0) {
                    int off = (b * C_ + c) * TX_ + idx;
                    vm = m_p[off];
                    vl = logs_p[off];
                }
                int o = (b * C_ + c) * TY_ + t;
                out_m[o] = vm;
                out_l[o] = vl;
            }
        }
        return;
    }

    // ================= zslice CTA (one per batch, no dp dependency) =================
    {
        const int b = bid - ZSL0_;
        int safe  = min(y_lengths[b], TY_);
        int idmax = max(safe - SEG_, 0);
        int ids   = (int)(rand_u[b] * ((float)idmax + 1e-8f));
        if (tid == 0) out_ids[b] = (float)ids;
#pragma unroll
        for (int i = 0; i < 12; i++) {
            int p = tid + i * 512;
            int k = p & (SEG_ - 1);
            int c = p >> 5;
            float vv = z[(b * C_ + c) * TY_ + ids + k];
            out_z[(b * C_ + c) * SEG_ + k] = (k < safe - ids) ? vv : 0.f;
        }
    }
}

// ---------------- launcher ----------------
extern "C" void kernel_launch(void* const* d_in, const int* in_sizes, int n_in,
                              void* d_out, int out_size)
{
    const float* z         = (const float*)d_in[0];
    const float* z_p       = (const float*)d_in[1];
    const float* m_p       = (const float*)d_in[2];
    const float* logs_p    = (const float*)d_in[3];
    const int*   x_lengths = (const int*)d_in[4];
    const int*   y_lengths = (const int*)d_in[5];
    const float* rand_u    = (const float*)d_in[6];

    float* out      = (float*)d_out;
    float* out_z    = out;                   // 16*192*32      = 98304
    float* out_ids  = out + 98304;           // 16
    float* out_attn = out + 98320;           // 16*2048*512    = 16777216
    float* out_m    = out + 16875536;        // 16*192*2048    = 6291456
    float* out_l    = out + 23166992;        // 16*192*2048    = 6291456
    (void)in_sizes; (void)n_in; (void)out_size;

    prep_kernel<<<(B_ * C_ * TX_ + 255) / 256, 256>>>(m_p, logs_p);
    cvec_kernel<<<B_, TX_>>>(m_p, logs_p);

    cudaFuncSetAttribute(fused_kernel, cudaFuncAttributeMaxDynamicSharedMemorySize, FUSED_SMEM);
    fused_kernel<<<NCTAS_, 512, FUSED_SMEM>>>(z_p, m_p, logs_p, z,
                                              x_lengths, y_lengths, rand_u,
                                              out_z, out_ids, out_attn, out_m, out_l);
}

// round 15
// speedup vs baseline: 1.2548x; 1.2548x over previous
#include <cuda_runtime.h>
#include <cuda_bf16.h>
#include <cstdint>

#define B_   16
#define C_   192
#define TX_  512
#define TY_  2048
#define SEG_ 32
#define K2_  384          // 2*C
#define NEG_INF_ (-1e9f)
#define CH_  16           // DP chunk rows staged in smem per phase
#define NLOAD_ 480        // dp loader lanes (15 warps)

// grid layout of fused kernel
#define GEMM0_   (B_)                 // 16
#define NGEMM_   512                  // 512 CTAs x 2 half-tiles = 1024 128x128 tiles
#define EPI0_    (GEMM0_ + NGEMM_)    // 528
#define EPB_     64                   // epilogue CTAs per batch
#define NEPI_    (B_ * EPB_)          // 1024
#define ZSL0_    (EPI0_ + NEPI_)      // 1552
#define NCTAS_   (ZSL0_ + B_)         // 1568

// dynamic smem: dp CTA -> dirs(128KB)+rowbuf(64KB); gemm CTA -> 2 x (As+Bs)(32KB each)
#define FUSED_SMEM (TY_ * 32 * 2 + 2 * CH_ * 128 * 16)

// ---------------- scratch (device globals: no runtime allocation) ----------------
__device__ float g_B[B_ * K2_ * TX_];
__device__ float g_cvec[B_ * TX_];
__device__ float g_negcent[(size_t)B_ * TY_ * TX_];  // 64 MB
__device__ int   g_idx[B_ * TY_];
__device__ int   g_cnt[B_ * 16];                     // per (b, 128-row band) completed n-tiles (target 4)
__device__ int   g_done[B_];                         // dp finished (g_idx valid) per batch

// ---------------- helpers ----------------
union F2 { float2 f; unsigned long long u; };

__device__ __forceinline__ unsigned long long ffma2(unsigned long long a,
                                                    unsigned long long b,
                                                    unsigned long long c) {
    unsigned long long d;
    asm("fma.rn.f32x2 %0, %1, %2, %3;" : "=l"(d) : "l"(a), "l"(b), "l"(c));
    return d;
}

__device__ __forceinline__ int ld_acq(const int* p) {
    int v;
    asm volatile("ld.acquire.gpu.global.b32 %0, [%1];" : "=r"(v) : "l"(p) : "memory");
    return v;
}
__device__ __forceinline__ void st_rel(int* p, int v) {
    asm volatile("st.release.gpu.global.b32 [%0], %1;" :: "l"(p), "r"(v) : "memory");
}

#define CP_ASYNC16(smem_u32, gptr) \
    asm volatile("cp.async.cg.shared.global [%0], [%1], 16;" :: "r"(smem_u32), "l"(gptr) : "memory")
#define CP_COMMIT() asm volatile("cp.async.commit_group;" ::: "memory")
#define CP_WAIT0()  asm volatile("cp.async.wait_group 0;" ::: "memory")
#define HBAR(id)    asm volatile("bar.sync %0, 256;" :: "r"(id) : "memory")

// ---------------- prep: B matrix + zero flags ----------------
__global__ void prep_kernel(const float* __restrict__ m_p, const float* __restrict__ logs_p) {
    int i = blockIdx.x * blockDim.x + threadIdx.x;   // over B*C*TX
    if (i >= B_ * C_ * TX_) return;
    if (i < B_ * 16) g_cnt[i] = 0;                   // reset producer flags every replay
    if (i < B_) g_done[i] = 0;
    int s = i % TX_;
    int c = (i / TX_) % C_;
    int b = i / (TX_ * C_);
    float lg = logs_p[i];
    float mp = m_p[i];
    float se = expf(-2.0f * lg);
    g_B[(b * K2_ + c) * TX_ + s]        = se;
    g_B[(b * K2_ + C_ + c) * TX_ + s]   = se * mp;
}

// ---------------- prep: per-column constant ----------------
__global__ void cvec_kernel(const float* __restrict__ m_p, const float* __restrict__ logs_p) {
    int b = blockIdx.x;
    int s = threadIdx.x;                              // 512 threads
    float acc = 0.f;
    for (int c = 0; c < C_; c++) {
        int off = (b * C_ + c) * TX_ + s;
        float lg = logs_p[off];
        float mp = m_p[off];
        float se = expf(-2.0f * lg);
        acc += -0.5f * se * mp * mp - lg;
    }
    g_cvec[b * TX_ + s] = acc;
}

// ---------------- fused: GEMM producers + DP consumers + gated epilogues ----------------
#define BM 128
#define BN 128
#define BK 16

// DP row update; direction bit = sign of (v[j] - v[j-1]).
__device__ __forceinline__ void dp_row(float4 (&cur)[4], float (&v)[16],
                                       unsigned short* dirs, int t, int lane)
{
    float sh = __shfl_up_sync(0xffffffffu, v[15], 1);
    float left0 = (lane == 0) ? NEG_INF_ : sh;

    float r[16];
    r[0]=cur[0].x;  r[1]=cur[0].y;  r[2]=cur[0].z;  r[3]=cur[0].w;
    r[4]=cur[1].x;  r[5]=cur[1].y;  r[6]=cur[1].z;  r[7]=cur[1].w;
    r[8]=cur[2].x;  r[9]=cur[2].y;  r[10]=cur[2].z; r[11]=cur[2].w;
    r[12]=cur[3].x; r[13]=cur[3].y; r[14]=cur[3].z; r[15]=cur[3].w;

    unsigned bits = 0u;
#pragma unroll
    for (int j = 15; j >= 1; j--) {
        float left = v[j - 1];
        float d = v[j] - left;                     // sign=1 <=> left > v[j]
        bits |= (__float_as_uint(d) >> (31 - j)) & (1u << j);
        v[j] = r[j] + fmaxf(left, v[j]);
    }
    float d0 = v[0] - left0;
    bits |= (__float_as_uint(d0) >> 31);
    v[0] = r[0] + fmaxf(left0, v[0]);

    dirs[t * 32 + lane] = (unsigned short)bits;
}

__global__ void __launch_bounds__(512) fused_kernel(const float* __restrict__ z_p,
                                                    const float* __restrict__ m_p,
                                                    const float* __restrict__ logs_p,
                                                    const float* __restrict__ z,
                                                    const int* __restrict__ x_lengths,
                                                    const int* __restrict__ y_lengths,
                                                    const float* __restrict__ rand_u,
                                                    float* __restrict__ out_z,
                                                    float* __restrict__ out_ids,
                                                    float* __restrict__ out_attn,
                                                    float* __restrict__ out_m,
                                                    float* __restrict__ out_l)
{
    extern __shared__ char sdyn[];
    const int tid = threadIdx.x;
    const unsigned bid = blockIdx.x;

    if (bid < GEMM0_) {
        // ================= DP consumer CTA (batch b): 1 compute warp + 15 loaders =================
        unsigned short* dirs = (unsigned short*)sdyn;                      // [TY_][32]
        float4* rowbuf = (float4*)(sdyn + (size_t)TY_ * 32 * 2);           // [2][CH_][128]

        const int b    = bid;
        const int lane = tid & 31;
        const int w    = tid >> 5;                                         // 0..15
        const int t_x  = min(x_lengths[b], TX_);
        const int t_y  = min(y_lengths[b], TY_);
        const int nch  = (t_y + CH_ - 1) / CH_;                            // <= 128 (16-row chunks)

        const float4* src = (const float4*)(g_negcent + (size_t)b * TY_ * TX_);
        const uint32_t rb_u32 = (uint32_t)__cvta_generic_to_shared(rowbuf);
        const int* cntb = g_cnt + b * 16;

        // ---- loader prologue: wait band 0 (rows 0..127), stream chunk 0 ----
        if (w > 0) {
            if (lane == 0) while (ld_acq(&cntb[0]) < 4) { }
            __syncwarp();
            const int lid = tid - 32;                                      // 0..479
            for (int p = lid; p < CH_ * 128; p += NLOAD_)
                CP_ASYNC16(rb_u32 + p * 16, src + (size_t)(p >> 7) * 128 + (p & 127));
            CP_COMMIT();
            CP_WAIT0();
        }

        float v[16];
#pragma unroll
        for (int j = 0; j < 16; j++) v[j] = NEG_INF_;
        if (tid == 0) v[0] = 0.0f;
        __syncthreads();

        for (int k = 0; k < nch; k++) {
            if (w > 0) {
                if (k + 1 < nch) {
                    const int c = k + 1;
                    if ((c & 7) == 0) {                                    // new 128-row band
                        if (lane == 0) while (ld_acq(&cntb[c >> 3]) < 4) { }
                        __syncwarp();
                    }
                    const int lid = tid - 32;
                    const int t0 = c * CH_;
                    const uint32_t dstb = rb_u32 + (uint32_t)((c & 1) * CH_ * 128 * 16);
                    for (int p = lid; p < CH_ * 128; p += NLOAD_)
                        CP_ASYNC16(dstb + p * 16, src + (size_t)(t0 + (p >> 7)) * 128 + (p & 127));
                    CP_COMMIT();
                    CP_WAIT0();
                }
            } else {
                const float4* bufb = rowbuf + (k & 1) * CH_ * 128 + lane * 4;
                const int tb = k * CH_;
                float4 cur[4], nxt[4];
                cur[0] = bufb[0]; cur[1] = bufb[1]; cur[2] = bufb[2]; cur[3] = bufb[3];
#pragma unroll
                for (int r = 0; r < CH_ - 1; r++) {
                    const float4* pn = bufb + (r + 1) * 128;
                    nxt[0] = pn[0]; nxt[1] = pn[1]; nxt[2] = pn[2]; nxt[3] = pn[3];
                    dp_row(cur, v, dirs, tb + r, lane);
                    cur[0] = nxt[0]; cur[1] = nxt[1]; cur[2] = nxt[2]; cur[3] = nxt[3];
                }
                dp_row(cur, v, dirs, tb + CH_ - 1, lane);
            }
            __syncthreads();
        }

        // rows >= t_y: no path
        for (int t = t_y + tid; t < TY_; t += 512) g_idx[b * TY_ + t] = -1;
        __syncthreads();

        // backtrack (single lane), then publish
        if (tid == 0) {
            int idx = t_x - 1;
            for (int j = t_y - 1; j >= 0; j--) {
                g_idx[b * TY_ + j] = idx;
                unsigned int word = dirs[j * 32 + (idx >> 4)];
                idx -= (int)((word >> (idx & 15)) & 1u);
            }
            __threadfence();
            st_rel(&g_done[b], 1);
        }
        return;
    }

    if (bid < EPI0_) {
        // ======== GEMM producer CTA: TWO independent 128x128 half-tiles ========
        // warps 0-7 -> tile 2r, warps 8-15 -> tile 2r+1; each half = R8's 256-thread loop
        // with its own smem double-buffer and a named barrier (ids 1 and 2).
        const int half = tid >> 8;                // 0 or 1
        const int htid = tid & 255;
        const int id   = (int)(bid - GEMM0_) * 2 + half;   // logical tile id
        const int nb   = id & 3;                  // 4 n-blocks
        const int b    = (id >> 2) & 15;          // 16 batches
        const int mblk = id >> 6;                 // 16 m-blocks of 128 rows (low bands first)
        const int m0   = mblk * BM;
        const int n0   = nb * BN;
        const int barid = 1 + half;

        typedef float TileT[BK][BM];
        TileT* As = (TileT*)(sdyn + half * 32768);               // [2][16][128] 16KB
        TileT* Bs = (TileT*)(sdyn + half * 32768 + 16384);       // [2][16][128] 16KB

        const bool active = (m0 < y_lengths[b]) && (n0 < x_lengths[b]);

        if (active) {
            const int kRow  = htid >> 4;              // 0..15
            const int lbase = (htid & 15) << 3;       // 0..120
            const int mBase = (htid >> 4) << 3;       // 8 rows
            const int nBase = (htid & 15) << 3;       // 8 cols

            const float* zpb = z_p + b * C_ * TY_;
            const float* Bb  = g_B + b * K2_ * TX_;

            F2 acc[8][4];
#pragma unroll
            for (int i = 0; i < 8; i++)
#pragma unroll
                for (int j = 0; j < 4; j++) { acc[i][j].f.x = 0.f; acc[i][j].f.y = 0.f; }

            float4 ra0, ra1, rb0, rb1;
            {
                int kk = kRow;
                int cA = (kk < C_) ? kk : kk - C_;
                const float* pA = zpb + cA * TY_ + m0 + lbase;
                ra0 = *(const float4*)pA;
                ra1 = *(const float4*)(pA + 4);
                if (kk < C_) {
                    ra0.x = -0.5f * ra0.x * ra0.x; ra0.y = -0.5f * ra0.y * ra0.y;
                    ra0.z = -0.5f * ra0.z * ra0.z; ra0.w = -0.5f * ra0.w * ra0.w;
                    ra1.x = -0.5f * ra1.x * ra1.x; ra1.y = -0.5f * ra1.y * ra1.y;
                    ra1.z = -0.5f * ra1.z * ra1.z; ra1.w = -0.5f * ra1.w * ra1.w;
                }
                const float* pB = Bb + kk * TX_ + n0 + lbase;
                rb0 = *(const float4*)pB;
                rb1 = *(const float4*)(pB + 4);
            }
            *(float4*)&As[0][kRow][lbase]     = ra0;
            *(float4*)&As[0][kRow][lbase + 4] = ra1;
            *(float4*)&Bs[0][kRow][lbase]     = rb0;
            *(float4*)&Bs[0][kRow][lbase + 4] = rb1;
            HBAR(barid);

            const int NIT = K2_ / BK;   // 24
            for (int it = 0; it < NIT; ++it) {
                const int cur = it & 1;
                if (it + 1 < NIT) {
                    int kk = (it + 1) * BK + kRow;
                    int cA = (kk < C_) ? kk : kk - C_;
                    const float* pA = zpb + cA * TY_ + m0 + lbase;
                    ra0 = *(const float4*)pA;
                    ra1 = *(const float4*)(pA + 4);
                    if (kk < C_) {
                        ra0.x = -0.5f * ra0.x * ra0.x; ra0.y = -0.5f * ra0.y * ra0.y;
                        ra0.z = -0.5f * ra0.z * ra0.z; ra0.w = -0.5f * ra0.w * ra0.w;
                        ra1.x = -0.5f * ra1.x * ra1.x; ra1.y = -0.5f * ra1.y * ra1.y;
                        ra1.z = -0.5f * ra1.z * ra1.z; ra1.w = -0.5f * ra1.w * ra1.w;
                    }
                    const float* pB = Bb + kk * TX_ + n0 + lbase;
                    rb0 = *(const float4*)pB;
                    rb1 = *(const float4*)(pB + 4);
                }
#pragma unroll
                for (int k = 0; k < BK; k++) {
                    float4 a0 = *(const float4*)&As[cur][k][mBase];
                    float4 a1 = *(const float4*)&As[cur][k][mBase + 4];
                    float4 b0 = *(const float4*)&Bs[cur][k][nBase];
                    float4 b1 = *(const float4*)&Bs[cur][k][nBase + 4];
                    F2 bb[4];
                    bb[0].f = make_float2(b0.x, b0.y);
                    bb[1].f = make_float2(b0.z, b0.w);
                    bb[2].f = make_float2(b1.x, b1.y);
                    bb[3].f = make_float2(b1.z, b1.w);
                    float a[8] = {a0.x, a0.y, a0.z, a0.w, a1.x, a1.y, a1.z, a1.w};
#pragma unroll
                    for (int i = 0; i < 8; i++) {
                        F2 aa; aa.f = make_float2(a[i], a[i]);
#pragma unroll
                        for (int j = 0; j < 4; j++)
                            acc[i][j].u = ffma2(aa.u, bb[j].u, acc[i][j].u);
                    }
                }
                if (it + 1 < NIT) {
                    const int nxt = cur ^ 1;
                    *(float4*)&As[nxt][kRow][lbase]     = ra0;
                    *(float4*)&As[nxt][kRow][lbase + 4] = ra1;
                    *(float4*)&Bs[nxt][kRow][lbase]     = rb0;
                    *(float4*)&Bs[nxt][kRow][lbase + 4] = rb1;
                }
                HBAR(barid);
            }

            // epilogue: add per-column constant and store
            float4 cv0 = *(const float4*)(g_cvec + b * TX_ + n0 + nBase);
            float4 cv1 = *(const float4*)(g_cvec + b * TX_ + n0 + nBase + 4);
            float* outbase = g_negcent + ((size_t)b * TY_ + m0 + mBase) * TX_ + n0 + nBase;
#pragma unroll
            for (int i = 0; i < 8; i++) {
                float4 o0, o1;
                o0.x = acc[i][0].f.x + cv0.x; o0.y = acc[i][0].f.y + cv0.y;
                o0.z = acc[i][1].f.x + cv0.z; o0.w = acc[i][1].f.y + cv0.w;
                o1.x = acc[i][2].f.x + cv1.x; o1.y = acc[i][2].f.y + cv1.y;
                o1.z = acc[i][3].f.x + cv1.z; o1.w = acc[i][3].f.y + cv1.w;
                float* op = outbase + (size_t)i * TX_;
                *(float4*)op       = o0;
                *(float4*)(op + 4) = o1;
            }
            HBAR(barid);
        }

        // signal band completion for this half-tile (also for skipped tiles)
        if (htid == 0) {
            __threadfence();
            atomicAdd(&g_cnt[b * 16 + mblk], 1);
        }
        return;
    }

    if (bid < ZSL0_) {
        // ================= gated epilogue CTA: attn rows + m/logs gathers =================
        const int e    = bid - EPI0_;
        const int b    = e >> 6;                  // 64 CTAs per batch
        const int part = e & 63;

        __shared__ int s_ready;
        if (tid == 0) {
            while (ld_acq(&g_done[b]) == 0) { }
            s_ready = 1;
        }
        __syncthreads();
        (void)s_ready;

        // attn: rows [part*32, part*32+32)
        {
            const int base = b * TY_ + part * 32;
#pragma unroll
            for (int i = 0; i < 8; i++) {
                int p   = tid + i * 512;              // 0..4095
                int t   = base + (p >> 7);
                int c4  = p & 127;
                int idx = g_idx[t];
                int s0  = c4 * 4;
                float4 val = make_float4(0.f, 0.f, 0.f, 0.f);
                if (idx >= s0 && idx < s0 + 4) {
                    if (idx == s0)          val.x = 1.f;
                    else if (idx == s0 + 1) val.y = 1.f;
                    else if (idx == s0 + 2) val.z = 1.f;
                    else                    val.w = 1.f;
                }
                *(float4*)(out_attn + (size_t)t * TX_ + s0) = val;
            }
        }

        // gather: elements [part*6144, +6144) of batch b's 192*2048
        {
            const int ebase = part * 6144;
#pragma unroll
            for (int i = 0; i < 12; i++) {
                int p = ebase + tid + i * 512;
                int t = p & (TY_ - 1);
                int c = p >> 11;
                int idx = g_idx[b * TY_ + t];
                float vm = 0.f, vl = 0.f;
                if (idx >= 0) {
                    int off = (b * C_ + c) * TX_ + idx;
                    vm = m_p[off];
                    vl = logs_p[off];
                }
                int o = (b * C_ + c) * TY_ + t;
                out_m[o] = vm;
                out_l[o] = vl;
            }
        }
        return;
    }

    // ================= zslice CTA (one per batch, no dp dependency) =================
    {
        const int b = bid - ZSL0_;
        int safe  = min(y_lengths[b], TY_);
        int idmax = max(safe - SEG_, 0);
        int ids   = (int)(rand_u[b] * ((float)idmax + 1e-8f));
        if (tid == 0) out_ids[b] = (float)ids;
#pragma unroll
        for (int i = 0; i < 12; i++) {
            int p = tid + i * 512;
            int k = p & (SEG_ - 1);
            int c = p >> 5;
            float vv = z[(b * C_ + c) * TY_ + ids + k];
            out_z[(b * C_ + c) * SEG_ + k] = (k < safe - ids) ? vv : 0.f;
        }
    }
}

// ---------------- launcher ----------------
extern "C" void kernel_launch(void* const* d_in, const int* in_sizes, int n_in,
                              void* d_out, int out_size)
{
    const float* z         = (const float*)d_in[0];
    const float* z_p       = (const float*)d_in[1];
    const float* m_p       = (const float*)d_in[2];
    const float* logs_p    = (const float*)d_in[3];
    const int*   x_lengths = (const int*)d_in[4];
    const int*   y_lengths = (const int*)d_in[5];
    const float* rand_u    = (const float*)d_in[6];

    float* out      = (float*)d_out;
    float* out_z    = out;                   // 16*192*32      = 98304
    float* out_ids  = out + 98304;           // 16
    float* out_attn = out + 98320;           // 16*2048*512    = 16777216
    float* out_m    = out + 16875536;        // 16*192*2048    = 6291456
    float* out_l    = out + 23166992;        // 16*192*2048    = 6291456
    (void)in_sizes; (void)n_in; (void)out_size;

    prep_kernel<<<(B_ * C_ * TX_ + 255) / 256, 256>>>(m_p, logs_p);
    cvec_kernel<<<B_, TX_>>>(m_p, logs_p);

    cudaFuncSetAttribute(fused_kernel, cudaFuncAttributeMaxDynamicSharedMemorySize, FUSED_SMEM);
    fused_kernel<<<NCTAS_, 512, FUSED_SMEM>>>(z_p, m_p, logs_p, z,
                                              x_lengths, y_lengths, rand_u,
                                              out_z, out_ids, out_attn, out_m, out_l);
}

// round 16
// speedup vs baseline: 1.2917x; 1.0294x over previous
#include <cuda_runtime.h>
#include <cuda_bf16.h>
#include <cstdint>

#define B_   16
#define C_   192
#define TX_  512
#define TY_  2048
#define SEG_ 32
#define K2_  384          // 2*C
#define NEG_INF_ (-1e9f)
#define CH_  16           // DP chunk rows staged in smem per phase
#define NLOAD_ 480        // dp loader lanes (15 warps)

// grid layout of fused kernel
#define PREP0_   (B_)                  // 16
#define NPREP_   192                   // 12 per batch
#define CVEC0_   (PREP0_ + NPREP_)     // 208
#define GEMMS_   (CVEC0_ + B_)         // 224
#define NGEMM_   512                   // x2 half-tiles = 1024 128x128 tiles
#define EPIS_    (GEMMS_ + NGEMM_)     // 736
#define NEPI_    (B_ * 64)             // 1024
#define ZSLS_    (EPIS_ + NEPI_)       // 1760
#define NCTAS_   (ZSLS_ + B_)          // 1776

// dynamic smem: dp CTA -> dirs(128KB)+rowbuf(64KB); gemm CTA -> 2 x (As+Bs)(32KB each)
#define FUSED_SMEM (TY_ * 32 * 2 + 2 * CH_ * 128 * 16)

// ---------------- scratch (device globals: no runtime allocation) ----------------
__device__ float g_B[B_ * K2_ * TX_];
__device__ float g_cvec[B_ * TX_];
__device__ float g_negcent[(size_t)B_ * TY_ * TX_];  // 64 MB
__device__ int   g_idx[B_ * TY_];
__device__ int   g_cnt[B_ * 16];     // per (b, 128-row band) completed n-half-tiles (target 4)
__device__ int   g_prep[B_];         // prep(12) + cvec(1) done (target 13)
__device__ int   g_btp[B_];          // backtrack rows finalized from top (1=presets done .. t_y=all)
__device__ int   g_epicnt[B_];       // finished epilogue CTAs (target 64; 64th resets flags)

// ---------------- helpers ----------------
union F2 { float2 f; unsigned long long u; };

__device__ __forceinline__ unsigned long long ffma2(unsigned long long a,
                                                    unsigned long long b,
                                                    unsigned long long c) {
    unsigned long long d;
    asm("fma.rn.f32x2 %0, %1, %2, %3;" : "=l"(d) : "l"(a), "l"(b), "l"(c));
    return d;
}

__device__ __forceinline__ int ld_acq(const int* p) {
    int v;
    asm volatile("ld.acquire.gpu.global.b32 %0, [%1];" : "=r"(v) : "l"(p) : "memory");
    return v;
}
__device__ __forceinline__ void st_rel(int* p, int v) {
    asm volatile("st.release.gpu.global.b32 [%0], %1;" :: "l"(p), "r"(v) : "memory");
}

#define CP_ASYNC16(smem_u32, gptr) \
    asm volatile("cp.async.cg.shared.global [%0], [%1], 16;" :: "r"(smem_u32), "l"(gptr) : "memory")
#define CP_COMMIT() asm volatile("cp.async.commit_group;" ::: "memory")
#define CP_WAIT0()  asm volatile("cp.async.wait_group 0;" ::: "memory")
#define HBAR(id)    asm volatile("bar.sync %0, 256;" :: "r"(id) : "memory")

// ---------------- fused: prep + cvec + GEMM producers + DP consumers + gated epilogues ----------------
#define BM 128
#define BN 128
#define BK 16

// DP row update; direction bit = sign of (v[j] - v[j-1]).
__device__ __forceinline__ void dp_row(float4 (&cur)[4], float (&v)[16],
                                       unsigned short* dirs, int t, int lane)
{
    float sh = __shfl_up_sync(0xffffffffu, v[15], 1);
    float left0 = (lane == 0) ? NEG_INF_ : sh;

    float r[16];
    r[0]=cur[0].x;  r[1]=cur[0].y;  r[2]=cur[0].z;  r[3]=cur[0].w;
    r[4]=cur[1].x;  r[5]=cur[1].y;  r[6]=cur[1].z;  r[7]=cur[1].w;
    r[8]=cur[2].x;  r[9]=cur[2].y;  r[10]=cur[2].z; r[11]=cur[2].w;
    r[12]=cur[3].x; r[13]=cur[3].y; r[14]=cur[3].z; r[15]=cur[3].w;

    unsigned bits = 0u;
#pragma unroll
    for (int j = 15; j >= 1; j--) {
        float left = v[j - 1];
        float d = v[j] - left;                     // sign=1 <=> left > v[j]
        bits |= (__float_as_uint(d) >> (31 - j)) & (1u << j);
        v[j] = r[j] + fmaxf(left, v[j]);
    }
    float d0 = v[0] - left0;
    bits |= (__float_as_uint(d0) >> 31);
    v[0] = r[0] + fmaxf(left0, v[0]);

    dirs[t * 32 + lane] = (unsigned short)bits;
}

__global__ void __launch_bounds__(512) fused_kernel(const float* __restrict__ z_p,
                                                    const float* __restrict__ m_p,
                                                    const float* __restrict__ logs_p,
                                                    const float* __restrict__ z,
                                                    const int* __restrict__ x_lengths,
                                                    const int* __restrict__ y_lengths,
                                                    const float* __restrict__ rand_u,
                                                    float* __restrict__ out_z,
                                                    float* __restrict__ out_ids,
                                                    float* __restrict__ out_attn,
                                                    float* __restrict__ out_m,
                                                    float* __restrict__ out_l)
{
    extern __shared__ char sdyn[];
    const int tid = threadIdx.x;
    const unsigned bid = blockIdx.x;

    if (bid < PREP0_) {
        // ================= DP consumer CTA (batch b): 1 compute warp + 15 loaders =================
        unsigned short* dirs = (unsigned short*)sdyn;                      // [TY_][32]
        float4* rowbuf = (float4*)(sdyn + (size_t)TY_ * 32 * 2);           // [2][CH_][128]

        const int b    = bid;
        const int lane = tid & 31;
        const int w    = tid >> 5;                                         // 0..15
        const int t_x  = min(x_lengths[b], TX_);
        const int t_y  = min(y_lengths[b], TY_);
        const int nch  = (t_y + CH_ - 1) / CH_;                            // <= 128 (16-row chunks)

        const float4* src = (const float4*)(g_negcent + (size_t)b * TY_ * TX_);
        const uint32_t rb_u32 = (uint32_t)__cvta_generic_to_shared(rowbuf);
        const int* cntb = g_cnt + b * 16;

        // ---- loader prologue: wait band 0 (rows 0..127), stream chunk 0 ----
        if (w > 0) {
            if (lane == 0) while (ld_acq(&cntb[0]) < 4) { }
            __syncwarp();
            const int lid = tid - 32;                                      // 0..479
            for (int p = lid; p < CH_ * 128; p += NLOAD_)
                CP_ASYNC16(rb_u32 + p * 16, src + (size_t)(p >> 7) * 128 + (p & 127));
            CP_COMMIT();
            CP_WAIT0();
        }

        float v[16];
#pragma unroll
        for (int j = 0; j < 16; j++) v[j] = NEG_INF_;
        if (tid == 0) v[0] = 0.0f;
        __syncthreads();

        for (int k = 0; k < nch; k++) {
            if (w > 0) {
                if (k + 1 < nch) {
                    const int c = k + 1;
                    if ((c & 7) == 0) {                                    // new 128-row band
                        if (lane == 0) while (ld_acq(&cntb[c >> 3]) < 4) { }
                        __syncwarp();
                    }
                    const int lid = tid - 32;
                    const int t0 = c * CH_;
                    const uint32_t dstb = rb_u32 + (uint32_t)((c & 1) * CH_ * 128 * 16);
                    for (int p = lid; p < CH_ * 128; p += NLOAD_)
                        CP_ASYNC16(dstb + p * 16, src + (size_t)(t0 + (p >> 7)) * 128 + (p & 127));
                    CP_COMMIT();
                    CP_WAIT0();
                }
            } else {
                const float4* bufb = rowbuf + (k & 1) * CH_ * 128 + lane * 4;
                const int tb = k * CH_;
                float4 cur[4], nxt[4];
                cur[0] = bufb[0]; cur[1] = bufb[1]; cur[2] = bufb[2]; cur[3] = bufb[3];
#pragma unroll
                for (int r = 0; r < CH_ - 1; r++) {
                    const float4* pn = bufb + (r + 1) * 128;
                    nxt[0] = pn[0]; nxt[1] = pn[1]; nxt[2] = pn[2]; nxt[3] = pn[3];
                    dp_row(cur, v, dirs, tb + r, lane);
                    cur[0] = nxt[0]; cur[1] = nxt[1]; cur[2] = nxt[2]; cur[3] = nxt[3];
                }
                dp_row(cur, v, dirs, tb + CH_ - 1, lane);
            }
            __syncthreads();
        }

        // rows >= t_y: no path (preset before any publish)
        for (int t = t_y + tid; t < TY_; t += 512) g_idx[b * TY_ + t] = -1;
        __syncthreads();

        // backtrack (single lane) with speculative word prefetch + progressive publish
        if (tid == 0) {
            __threadfence();
            st_rel(&g_btp[b], 1);                                          // presets visible

            const int base = b * TY_;
            int idx = t_x - 1;
            unsigned w0, w1;
            unsigned wv = dirs[(t_y - 1) * 32 + (idx >> 4)];
            for (int j = t_y - 1; j > 0; j--) {
                g_idx[base + j] = idx;
                const int idxm = (idx > 0) ? idx - 1 : 0;
                w0 = dirs[(j - 1) * 32 + (idx >> 4)];                      // spec: bit=0 word
                w1 = dirs[(j - 1) * 32 + (idxm >> 4)];                     // spec: bit=1 word
                unsigned bit = (wv >> (idx & 15)) & 1u;
                idx -= (int)bit;
                wv = bit ? w1 : w0;
                if ((j & 255) == 0) { __threadfence(); st_rel(&g_btp[b], t_y - j); }
            }
            g_idx[base] = idx;
            __threadfence();
            st_rel(&g_btp[b], t_y);                                        // all rows final
        }
        return;
    }

    if (bid < CVEC0_) {
        // ================= prep CTA: build g_B slice for batch b =================
        const int pi  = bid - PREP0_;
        const int b   = pi / 12;
        const int sub = pi % 12;
        const int e0  = sub * 8192;                 // of C_*TX_ = 98304 elements
#pragma unroll
        for (int i = 0; i < 16; i++) {
            int e = e0 + tid + i * 512;
            int c = e >> 9;                          // /512
            int s = e & 511;
            int off = (b * C_ + c) * TX_ + s;
            float lg = logs_p[off];
            float mp = m_p[off];
            float se = expf(-2.0f * lg);
            g_B[(b * K2_ + c) * TX_ + s]      = se;
            g_B[(b * K2_ + C_ + c) * TX_ + s] = se * mp;
        }
        __syncthreads();
        if (tid == 0) { __threadfence(); atomicAdd(&g_prep[b], 1); }
        return;
    }

    if (bid < GEMMS_) {
        // ================= cvec CTA: per-column constant for batch b =================
        const int b = bid - CVEC0_;
        const int s = tid;                           // 512 columns
        float acc = 0.f;
        for (int c = 0; c < C_; c++) {
            int off = (b * C_ + c) * TX_ + s;
            float lg = logs_p[off];
            float mp = m_p[off];
            float se = expf(-2.0f * lg);
            acc += -0.5f * se * mp * mp - lg;
        }
        g_cvec[b * TX_ + s] = acc;
        __syncthreads();
        if (tid == 0) { __threadfence(); atomicAdd(&g_prep[b], 1); }
        return;
    }

    if (bid < EPIS_) {
        // ======== GEMM producer CTA: TWO independent 128x128 half-tiles ========
        const int half = tid >> 8;                // 0 or 1
        const int htid = tid & 255;
        const int id   = (int)(bid - GEMMS_) * 2 + half;   // logical tile id
        const int nb   = id & 3;                  // 4 n-blocks
        const int b    = (id >> 2) & 15;          // 16 batches (same for both halves)
        const int mblk = id >> 6;                 // 16 m-blocks of 128 rows (low bands first)
        const int m0   = mblk * BM;
        const int n0   = nb * BN;
        const int barid = 1 + half;

        // gate on prep+cvec of this batch (12 + 1)
        if (tid == 0) { while (ld_acq(&g_prep[b]) < 13) { } }
        __syncthreads();

        typedef float TileT[BK][BM];
        TileT* As = (TileT*)(sdyn + half * 32768);               // [2][16][128] 16KB
        TileT* Bs = (TileT*)(sdyn + half * 32768 + 16384);       // [2][16][128] 16KB

        const bool active = (m0 < y_lengths[b]) && (n0 < x_lengths[b]);

        if (active) {
            const int kRow  = htid >> 4;              // 0..15
            const int lbase = (htid & 15) << 3;       // 0..120
            const int mBase = (htid >> 4) << 3;       // 8 rows
            const int nBase = (htid & 15) << 3;       // 8 cols

            const float* zpb = z_p + b * C_ * TY_;
            const float* Bb  = g_B + b * K2_ * TX_;

            F2 acc[8][4];
#pragma unroll
            for (int i = 0; i < 8; i++)
#pragma unroll
                for (int j = 0; j < 4; j++) { acc[i][j].f.x = 0.f; acc[i][j].f.y = 0.f; }

            float4 ra0, ra1, rb0, rb1;
            {
                int kk = kRow;
                int cA = (kk < C_) ? kk : kk - C_;
                const float* pA = zpb + cA * TY_ + m0 + lbase;
                ra0 = *(const float4*)pA;
                ra1 = *(const float4*)(pA + 4);
                if (kk < C_) {
                    ra0.x = -0.5f * ra0.x * ra0.x; ra0.y = -0.5f * ra0.y * ra0.y;
                    ra0.z = -0.5f * ra0.z * ra0.z; ra0.w = -0.5f * ra0.w * ra0.w;
                    ra1.x = -0.5f * ra1.x * ra1.x; ra1.y = -0.5f * ra1.y * ra1.y;
                    ra1.z = -0.5f * ra1.z * ra1.z; ra1.w = -0.5f * ra1.w * ra1.w;
                }
                const float* pB = Bb + kk * TX_ + n0 + lbase;
                rb0 = *(const float4*)pB;
                rb1 = *(const float4*)(pB + 4);
            }
            *(float4*)&As[0][kRow][lbase]     = ra0;
            *(float4*)&As[0][kRow][lbase + 4] = ra1;
            *(float4*)&Bs[0][kRow][lbase]     = rb0;
            *(float4*)&Bs[0][kRow][lbase + 4] = rb1;
            HBAR(barid);

            const int NIT = K2_ / BK;   // 24
            for (int it = 0; it < NIT; ++it) {
                const int cur = it & 1;
                if (it + 1 < NIT) {
                    int kk = (it + 1) * BK + kRow;
                    int cA = (kk < C_) ? kk : kk - C_;
                    const float* pA = zpb + cA * TY_ + m0 + lbase;
                    ra0 = *(const float4*)pA;
                    ra1 = *(const float4*)(pA + 4);
                    if (kk < C_) {
                        ra0.x = -0.5f * ra0.x * ra0.x; ra0.y = -0.5f * ra0.y * ra0.y;
                        ra0.z = -0.5f * ra0.z * ra0.z; ra0.w = -0.5f * ra0.w * ra0.w;
                        ra1.x = -0.5f * ra1.x * ra1.x; ra1.y = -0.5f * ra1.y * ra1.y;
                        ra1.z = -0.5f * ra1.z * ra1.z; ra1.w = -0.5f * ra1.w * ra1.w;
                    }
                    const float* pB = Bb + kk * TX_ + n0 + lbase;
                    rb0 = *(const float4*)pB;
                    rb1 = *(const float4*)(pB + 4);
                }
#pragma unroll
                for (int k = 0; k < BK; k++) {
                    float4 a0 = *(const float4*)&As[cur][k][mBase];
                    float4 a1 = *(const float4*)&As[cur][k][mBase + 4];
                    float4 b0 = *(const float4*)&Bs[cur][k][nBase];
                    float4 b1 = *(const float4*)&Bs[cur][k][nBase + 4];
                    F2 bb[4];
                    bb[0].f = make_float2(b0.x, b0.y);
                    bb[1].f = make_float2(b0.z, b0.w);
                    bb[2].f = make_float2(b1.x, b1.y);
                    bb[3].f = make_float2(b1.z, b1.w);
                    float a[8] = {a0.x, a0.y, a0.z, a0.w, a1.x, a1.y, a1.z, a1.w};
#pragma unroll
                    for (int i = 0; i < 8; i++) {
                        F2 aa; aa.f = make_float2(a[i], a[i]);
#pragma unroll
                        for (int j = 0; j < 4; j++)
                            acc[i][j].u = ffma2(aa.u, bb[j].u, acc[i][j].u);
                    }
                }
                if (it + 1 < NIT) {
                    const int nxt = cur ^ 1;
                    *(float4*)&As[nxt][kRow][lbase]     = ra0;
                    *(float4*)&As[nxt][kRow][lbase + 4] = ra1;
                    *(float4*)&Bs[nxt][kRow][lbase]     = rb0;
                    *(float4*)&Bs[nxt][kRow][lbase + 4] = rb1;
                }
                HBAR(barid);
            }

            // epilogue: add per-column constant and store
            float4 cv0 = *(const float4*)(g_cvec + b * TX_ + n0 + nBase);
            float4 cv1 = *(const float4*)(g_cvec + b * TX_ + n0 + nBase + 4);
            float* outbase = g_negcent + ((size_t)b * TY_ + m0 + mBase) * TX_ + n0 + nBase;
#pragma unroll
            for (int i = 0; i < 8; i++) {
                float4 o0, o1;
                o0.x = acc[i][0].f.x + cv0.x; o0.y = acc[i][0].f.y + cv0.y;
                o0.z = acc[i][1].f.x + cv0.z; o0.w = acc[i][1].f.y + cv0.w;
                o1.x = acc[i][2].f.x + cv1.x; o1.y = acc[i][2].f.y + cv1.y;
                o1.z = acc[i][3].f.x + cv1.z; o1.w = acc[i][3].f.y + cv1.w;
                float* op = outbase + (size_t)i * TX_;
                *(float4*)op       = o0;
                *(float4*)(op + 4) = o1;
            }
            HBAR(barid);
        }

        // signal band completion for this half-tile (also for skipped tiles)
        if (htid == 0) {
            __threadfence();
            atomicAdd(&g_cnt[b * 16 + mblk], 1);
        }
        return;
    }

    if (bid < ZSLS_) {
        // ================= gated epilogue CTA: 32-row t-slice of attn + gathers =================
        const int e    = bid - EPIS_;
        const int b    = e >> 6;                  // 64 CTAs per batch
        const int part = e & 63;
        const int t0   = part * 32;

        const int t_yb = min(y_lengths[b], TY_);
        int need = t_yb - t0;
        if (need < 1) need = 1;

        __shared__ int s_ready;
        if (tid == 0) {
            while (ld_acq(&g_btp[b]) < need) { }
            s_ready = 1;
        }
        __syncthreads();
        (void)s_ready;

        // attn: rows [t0, t0+32)
        {
            const int base = b * TY_ + t0;
#pragma unroll
            for (int i = 0; i < 8; i++) {
                int p   = tid + i * 512;              // 0..4095
                int t   = base + (p >> 7);
                int c4  = p & 127;
                int idx = g_idx[t];
                int s0  = c4 * 4;
                float4 val = make_float4(0.f, 0.f, 0.f, 0.f);
                if (idx >= s0 && idx < s0 + 4) {
                    if (idx == s0)          val.x = 1.f;
                    else if (idx == s0 + 1) val.y = 1.f;
                    else if (idx == s0 + 2) val.z = 1.f;
                    else                    val.w = 1.f;
                }
                *(float4*)(out_attn + (size_t)t * TX_ + s0) = val;
            }
        }

        // gather: all 192 channels, rows [t0, t0+32)  (6144 elements)
        {
#pragma unroll
            for (int i = 0; i < 12; i++) {
                int p  = tid + i * 512;
                int c  = p >> 5;
                int tl = p & 31;
                int t  = t0 + tl;
                int idx = g_idx[b * TY_ + t];
                float vm = 0.f, vl = 0.f;
                if (idx >= 0) {
                    int off = (b * C_ + c) * TX_ + idx;
                    vm = m_p[off];
                    vl = logs_p[off];
                }
                int o = (b * C_ + c) * TY_ + t;
                out_m[o] = vm;
                out_l[o] = vl;
            }
        }

        // cleanup: the 64th epilogue CTA of batch b resets all flags for the next replay
        __syncthreads();
        if (tid == 0) {
            int old = atomicAdd(&g_epicnt[b], 1);
            if (old == 63) {
                g_prep[b] = 0;
                g_btp[b]  = 0;
                g_epicnt[b] = 0;
#pragma unroll
                for (int i = 0; i < 16; i++) g_cnt[b * 16 + i] = 0;
            }
        }
        return;
    }

    // ================= zslice CTA (one per batch, no dp dependency) =================
    {
        const int b = bid - ZSLS_;
        int safe  = min(y_lengths[b], TY_);
        int idmax = max(safe - SEG_, 0);
        int ids   = (int)(rand_u[b] * ((float)idmax + 1e-8f));
        if (tid == 0) out_ids[b] = (float)ids;
#pragma unroll
        for (int i = 0; i < 12; i++) {
            int p = tid + i * 512;
            int k = p & (SEG_ - 1);
            int c = p >> 5;
            float vv = z[(b * C_ + c) * TY_ + ids + k];
            out_z[(b * C_ + c) * SEG_ + k] = (k < safe - ids) ? vv : 0.f;
        }
    }
}

// ---------------- launcher ----------------
extern "C" void kernel_launch(void* const* d_in, const int* in_sizes, int n_in,
                              void* d_out, int out_size)
{
    const float* z         = (const float*)d_in[0];
    const float* z_p       = (const float*)d_in[1];
    const float* m_p       = (const float*)d_in[2];
    const float* logs_p    = (const float*)d_in[3];
    const int*   x_lengths = (const int*)d_in[4];
    const int*   y_lengths = (const int*)d_in[5];
    const float* rand_u    = (const float*)d_in[6];

    float* out      = (float*)d_out;
    float* out_z    = out;                   // 16*192*32      = 98304
    float* out_ids  = out + 98304;           // 16
    float* out_attn = out + 98320;           // 16*2048*512    = 16777216
    float* out_m    = out + 16875536;        // 16*192*2048    = 6291456
    float* out_l    = out + 23166992;        // 16*192*2048    = 6291456
    (void)in_sizes; (void)n_in; (void)out_size;

    cudaFuncSetAttribute(fused_kernel, cudaFuncAttributeMaxDynamicSharedMemorySize, FUSED_SMEM);
    fused_kernel<<<NCTAS_, 512, FUSED_SMEM>>>(z_p, m_p, logs_p, z,
                                              x_lengths, y_lengths, rand_u,
                                              out_z, out_ids, out_attn, out_m, out_l);
}